// round 1
// baseline (speedup 1.0000x reference)
#include <cuda_runtime.h>

#define DIM     768
#define NHEADS  12
#define HDIM    64
#define BATCH   8
#define SEQ     1024
#define MTOT    (BATCH * SEQ)      // 8192
#define QKVN    (3 * DIM)          // 2304
#define ATT_SCALE 0.125f           // 64^-0.5

// Scratch (allocation-free rule: __device__ globals)
__device__ float g_q[BATCH * NHEADS * SEQ * HDIM];
__device__ float g_k[BATCH * NHEADS * SEQ * HDIM];
__device__ float g_v[BATCH * NHEADS * SEQ * HDIM];
__device__ float g_attn[BATCH * SEQ * DIM];

// ---------------------------------------------------------------------------
// Kernel 1: qkv = x @ w_qkv^T, scatter into q/k/v [B,H,N,D]
// 128x128x16 tile, 256 threads, 8x8 per thread.
// ---------------------------------------------------------------------------
__global__ __launch_bounds__(256, 1)
void qkv_gemm_kernel(const float* __restrict__ X, const float* __restrict__ W)
{
    __shared__ float As[16][128];
    __shared__ float Bs[16][128];

    const int tid = threadIdx.x;
    const int m0  = blockIdx.y * 128;
    const int n0  = blockIdx.x * 128;
    const int ty  = tid >> 4;
    const int tx  = tid & 15;

    float acc[8][8];
#pragma unroll
    for (int i = 0; i < 8; i++)
#pragma unroll
        for (int j = 0; j < 8; j++) acc[i][j] = 0.f;

    const int lr = tid >> 2;            // 0..63
    const int lc = (tid & 3) << 2;      // 0,4,8,12
    const float* Ap = X + (size_t)(m0 + lr) * DIM + lc;
    const float* Bp = W + (size_t)(n0 + lr) * DIM + lc;

    for (int k0 = 0; k0 < DIM; k0 += 16) {
        float4 a0 = *(const float4*)(Ap + k0);
        float4 a1 = *(const float4*)(Ap + (size_t)64 * DIM + k0);
        float4 b0 = *(const float4*)(Bp + k0);
        float4 b1 = *(const float4*)(Bp + (size_t)64 * DIM + k0);
        __syncthreads();
        As[lc + 0][lr]      = a0.x; As[lc + 1][lr]      = a0.y;
        As[lc + 2][lr]      = a0.z; As[lc + 3][lr]      = a0.w;
        As[lc + 0][lr + 64] = a1.x; As[lc + 1][lr + 64] = a1.y;
        As[lc + 2][lr + 64] = a1.z; As[lc + 3][lr + 64] = a1.w;
        Bs[lc + 0][lr]      = b0.x; Bs[lc + 1][lr]      = b0.y;
        Bs[lc + 2][lr]      = b0.z; Bs[lc + 3][lr]      = b0.w;
        Bs[lc + 0][lr + 64] = b1.x; Bs[lc + 1][lr + 64] = b1.y;
        Bs[lc + 2][lr + 64] = b1.z; Bs[lc + 3][lr + 64] = b1.w;
        __syncthreads();
#pragma unroll
        for (int k = 0; k < 16; k++) {
            float a[8], b[8];
            *(float4*)&a[0] = *(const float4*)&As[k][ty * 8];
            *(float4*)&a[4] = *(const float4*)&As[k][ty * 8 + 4];
            *(float4*)&b[0] = *(const float4*)&Bs[k][tx * 8];
            *(float4*)&b[4] = *(const float4*)&Bs[k][tx * 8 + 4];
#pragma unroll
            for (int i = 0; i < 8; i++)
#pragma unroll
                for (int j = 0; j < 8; j++)
                    acc[i][j] += a[i] * b[j];
        }
    }

    // Scatter: column axis decomposes as (3, H, D). Tiles never straddle the
    // 768 boundary (768 % 128 == 0) nor the 64 boundary per-thread (8 | 64).
    const int sel = n0 / DIM;
    float* dst = sel == 0 ? g_q : (sel == 1 ? g_k : g_v);
    const int rb = (n0 % DIM) + tx * 8;
    const int h  = rb >> 6;
    const int d0 = rb & 63;
#pragma unroll
    for (int i = 0; i < 8; i++) {
        const int m = m0 + ty * 8 + i;
        const int b = m >> 10;
        const int n = m & 1023;
        float* p = dst + ((size_t)((b * NHEADS + h) * SEQ + n)) * HDIM + d0;
        *(float4*)p       = make_float4(acc[i][0], acc[i][1], acc[i][2], acc[i][3]);
        *(float4*)(p + 4) = make_float4(acc[i][4], acc[i][5], acc[i][6], acc[i][7]);
    }
}

// ---------------------------------------------------------------------------
// Kernel 2: fused flash-style attention per (b, h, 128-query tile)
// 256 threads. S tile 128x128 register-computed, online softmax in SMEM,
// O accumulated in registers (8 rows x 4 cols per thread).
// ---------------------------------------------------------------------------
#define QS_STRIDE 132   // [64][132] d-major Q/K (16B-aligned rows for float4)
#define VS_STRIDE 68    // [128][68]
#define SS_STRIDE 129   // [128][129] (conflict-free per-row scans)

#define SM_QS   0
#define SM_KS   (64 * QS_STRIDE)
#define SM_VS   (SM_KS + 64 * QS_STRIDE)
#define SM_SS   (SM_VS + 128 * VS_STRIDE)
#define SM_FAC  (SM_SS + 128 * SS_STRIDE)
#define SM_MROW (SM_FAC + 128)
#define SM_LROW (SM_MROW + 128)
#define SMEM_FLOATS (SM_LROW + 128)
#define SMEM_BYTES (SMEM_FLOATS * 4)

__global__ __launch_bounds__(256, 1)
void attn_kernel()
{
    extern __shared__ float sm[];
    float* Qs   = sm + SM_QS;
    float* Ks   = sm + SM_KS;
    float* Vs   = sm + SM_VS;
    float* Ss   = sm + SM_SS;
    float* facs = sm + SM_FAC;
    float* mrow = sm + SM_MROW;
    float* lrow = sm + SM_LROW;

    const int tid = threadIdx.x;
    const int bh  = blockIdx.x;                  // 0..95
    const int qt  = blockIdx.y;                  // 0..7
    const float* Qg = g_q + (size_t)bh * SEQ * HDIM + (size_t)qt * 128 * HDIM;
    const float* Kg = g_k + (size_t)bh * SEQ * HDIM;
    const float* Vg = g_v + (size_t)bh * SEQ * HDIM;

    // Load Q tile transposed (d-major)
    for (int p = tid; p < 128 * 16; p += 256) {
        const int r  = p >> 4;
        const int c4 = (p & 15) << 2;
        float4 qv = *(const float4*)(Qg + (size_t)r * HDIM + c4);
        Qs[(c4 + 0) * QS_STRIDE + r] = qv.x;
        Qs[(c4 + 1) * QS_STRIDE + r] = qv.y;
        Qs[(c4 + 2) * QS_STRIDE + r] = qv.z;
        Qs[(c4 + 3) * QS_STRIDE + r] = qv.w;
    }
    if (tid < 128) { mrow[tid] = -1e30f; lrow[tid] = 0.f; }

    const int ty = tid >> 4;
    const int tx = tid & 15;
    float o[8][4];
#pragma unroll
    for (int i = 0; i < 8; i++)
#pragma unroll
        for (int j = 0; j < 4; j++) o[i][j] = 0.f;

    for (int j0 = 0; j0 < SEQ; j0 += 128) {
        __syncthreads();  // previous PV readers done; Q load visible (iter 0)
        // Load K tile transposed + V tile direct
        for (int p = tid; p < 128 * 16; p += 256) {
            const int r  = p >> 4;
            const int c4 = (p & 15) << 2;
            float4 kv = *(const float4*)(Kg + (size_t)(j0 + r) * HDIM + c4);
            Ks[(c4 + 0) * QS_STRIDE + r] = kv.x;
            Ks[(c4 + 1) * QS_STRIDE + r] = kv.y;
            Ks[(c4 + 2) * QS_STRIDE + r] = kv.z;
            Ks[(c4 + 3) * QS_STRIDE + r] = kv.w;
            float4 vv = *(const float4*)(Vg + (size_t)(j0 + r) * HDIM + c4);
            *(float4*)&Vs[r * VS_STRIDE + c4] = vv;
        }
        __syncthreads();

        // S = (Q K^T) * scale
        float s[8][8];
#pragma unroll
        for (int i = 0; i < 8; i++)
#pragma unroll
            for (int j = 0; j < 8; j++) s[i][j] = 0.f;
#pragma unroll 8
        for (int d = 0; d < HDIM; d++) {
            float a[8], b[8];
            *(float4*)&a[0] = *(const float4*)&Qs[d * QS_STRIDE + ty * 8];
            *(float4*)&a[4] = *(const float4*)&Qs[d * QS_STRIDE + ty * 8 + 4];
            *(float4*)&b[0] = *(const float4*)&Ks[d * QS_STRIDE + tx * 8];
            *(float4*)&b[4] = *(const float4*)&Ks[d * QS_STRIDE + tx * 8 + 4];
#pragma unroll
            for (int i = 0; i < 8; i++)
#pragma unroll
                for (int j = 0; j < 8; j++)
                    s[i][j] += a[i] * b[j];
        }
#pragma unroll
        for (int i = 0; i < 8; i++)
#pragma unroll
            for (int j = 0; j < 8; j++)
                Ss[(ty * 8 + i) * SS_STRIDE + tx * 8 + j] = s[i][j] * ATT_SCALE;
        __syncthreads();

        // Online softmax row update (one thread per row)
        if (tid < 128) {
            float* row = &Ss[tid * SS_STRIDE];
            const float mold = mrow[tid];
            float mx = mold;
#pragma unroll 8
            for (int c = 0; c < 128; c++) mx = fmaxf(mx, row[c]);
            const float fac = __expf(mold - mx);
            float sum = 0.f;
#pragma unroll 8
            for (int c = 0; c < 128; c++) {
                const float e = __expf(row[c] - mx);
                row[c] = e;
                sum += e;
            }
            lrow[tid] = lrow[tid] * fac + sum;
            mrow[tid] = mx;
            facs[tid] = fac;
        }
        __syncthreads();

        // Rescale running O and accumulate O += P @ V
        float f[8];
#pragma unroll
        for (int i = 0; i < 8; i++) f[i] = facs[ty * 8 + i];
#pragma unroll
        for (int i = 0; i < 8; i++)
#pragma unroll
            for (int j = 0; j < 4; j++) o[i][j] *= f[i];

#pragma unroll 4
        for (int kc = 0; kc < 128; kc++) {
            float4 vv = *(const float4*)&Vs[kc * VS_STRIDE + tx * 4];
            float p[8];
#pragma unroll
            for (int i = 0; i < 8; i++) p[i] = Ss[(ty * 8 + i) * SS_STRIDE + kc];
#pragma unroll
            for (int i = 0; i < 8; i++) {
                o[i][0] += p[i] * vv.x;
                o[i][1] += p[i] * vv.y;
                o[i][2] += p[i] * vv.z;
                o[i][3] += p[i] * vv.w;
            }
        }
    }

    // Epilogue: normalize and write to g_attn laid out [B, N, C]
    const int h = bh % NHEADS;
    const int b = bh / NHEADS;
#pragma unroll
    for (int i = 0; i < 8; i++) {
        const float linv = 1.f / lrow[ty * 8 + i];
        const int n = qt * 128 + ty * 8 + i;
        float4 ov = make_float4(o[i][0] * linv, o[i][1] * linv,
                                o[i][2] * linv, o[i][3] * linv);
        *(float4*)(g_attn + ((size_t)(b * SEQ + n)) * DIM + h * HDIM + tx * 4) = ov;
    }
}

// ---------------------------------------------------------------------------
// Kernel 3: out = attn_out @ w_proj^T + b_proj
// ---------------------------------------------------------------------------
__global__ __launch_bounds__(256, 1)
void proj_gemm_kernel(const float* __restrict__ W, const float* __restrict__ bias,
                      float* __restrict__ OUT)
{
    __shared__ float As[16][128];
    __shared__ float Bs[16][128];

    const int tid = threadIdx.x;
    const int m0  = blockIdx.y * 128;
    const int n0  = blockIdx.x * 128;
    const int ty  = tid >> 4;
    const int tx  = tid & 15;

    float acc[8][8];
#pragma unroll
    for (int i = 0; i < 8; i++)
#pragma unroll
        for (int j = 0; j < 8; j++) acc[i][j] = 0.f;

    const int lr = tid >> 2;
    const int lc = (tid & 3) << 2;
    const float* Ap = g_attn + (size_t)(m0 + lr) * DIM + lc;
    const float* Bp = W + (size_t)(n0 + lr) * DIM + lc;

    for (int k0 = 0; k0 < DIM; k0 += 16) {
        float4 a0 = *(const float4*)(Ap + k0);
        float4 a1 = *(const float4*)(Ap + (size_t)64 * DIM + k0);
        float4 b0 = *(const float4*)(Bp + k0);
        float4 b1 = *(const float4*)(Bp + (size_t)64 * DIM + k0);
        __syncthreads();
        As[lc + 0][lr]      = a0.x; As[lc + 1][lr]      = a0.y;
        As[lc + 2][lr]      = a0.z; As[lc + 3][lr]      = a0.w;
        As[lc + 0][lr + 64] = a1.x; As[lc + 1][lr + 64] = a1.y;
        As[lc + 2][lr + 64] = a1.z; As[lc + 3][lr + 64] = a1.w;
        Bs[lc + 0][lr]      = b0.x; Bs[lc + 1][lr]      = b0.y;
        Bs[lc + 2][lr]      = b0.z; Bs[lc + 3][lr]      = b0.w;
        Bs[lc + 0][lr + 64] = b1.x; Bs[lc + 1][lr + 64] = b1.y;
        Bs[lc + 2][lr + 64] = b1.z; Bs[lc + 3][lr + 64] = b1.w;
        __syncthreads();
#pragma unroll
        for (int k = 0; k < 16; k++) {
            float a[8], b[8];
            *(float4*)&a[0] = *(const float4*)&As[k][ty * 8];
            *(float4*)&a[4] = *(const float4*)&As[k][ty * 8 + 4];
            *(float4*)&b[0] = *(const float4*)&Bs[k][tx * 8];
            *(float4*)&b[4] = *(const float4*)&Bs[k][tx * 8 + 4];
#pragma unroll
            for (int i = 0; i < 8; i++)
#pragma unroll
                for (int j = 0; j < 8; j++)
                    acc[i][j] += a[i] * b[j];
        }
    }

    const int ob = n0 + tx * 8;
    float bv[8];
    *(float4*)&bv[0] = *(const float4*)(bias + ob);
    *(float4*)&bv[4] = *(const float4*)(bias + ob + 4);
#pragma unroll
    for (int i = 0; i < 8; i++) {
        const int m = m0 + ty * 8 + i;
        float* p = OUT + (size_t)m * DIM + ob;
        *(float4*)p = make_float4(acc[i][0] + bv[0], acc[i][1] + bv[1],
                                  acc[i][2] + bv[2], acc[i][3] + bv[3]);
        *(float4*)(p + 4) = make_float4(acc[i][4] + bv[4], acc[i][5] + bv[5],
                                        acc[i][6] + bv[6], acc[i][7] + bv[7]);
    }
}

// ---------------------------------------------------------------------------
extern "C" void kernel_launch(void* const* d_in, const int* in_sizes, int n_in,
                              void* d_out, int out_size)
{
    (void)in_sizes; (void)n_in; (void)out_size;
    const float* x      = (const float*)d_in[0];
    const float* w_qkv  = (const float*)d_in[1];
    const float* w_proj = (const float*)d_in[2];
    const float* b_proj = (const float*)d_in[3];
    float* out = (float*)d_out;

    // Opt-in to >48KB dynamic SMEM for the attention kernel (host-side,
    // idempotent, not a stream op — safe under graph capture).
    cudaFuncSetAttribute(attn_kernel, cudaFuncAttributeMaxDynamicSharedMemorySize,
                         SMEM_BYTES);

    qkv_gemm_kernel<<<dim3(QKVN / 128, MTOT / 128), 256>>>(x, w_qkv);
    attn_kernel<<<dim3(BATCH * NHEADS, SEQ / 128), 256, SMEM_BYTES>>>();
    proj_gemm_kernel<<<dim3(DIM / 128, MTOT / 128), 256>>>(w_proj, b_proj, out);
}

// round 3
// speedup vs baseline: 1.5696x; 1.5696x over previous
#include <cuda_runtime.h>
#include <cuda_fp16.h>
#include <cstdint>

#define DIM     768
#define NHEADS  12
#define HDIM    64
#define BATCH   8
#define SEQ     1024
#define MTOT    (BATCH * SEQ)      // 8192
#define QKVN    (3 * DIM)          // 2304
#define ATT_SCALE 0.125f

// ---------------------------------------------------------------------------
// Scratch (__device__ globals; no allocations allowed)
// ---------------------------------------------------------------------------
__device__ float g_q[BATCH * NHEADS * SEQ * HDIM];
__device__ float g_k[BATCH * NHEADS * SEQ * HDIM];
__device__ float g_v[BATCH * NHEADS * SEQ * HDIM];
__device__ __half g_xh[MTOT * DIM], g_xl[MTOT * DIM];
__device__ __half g_wqh[QKVN * DIM], g_wql[QKVN * DIM];
__device__ __half g_wph[DIM * DIM],  g_wpl[DIM * DIM];
__device__ __half g_ah[MTOT * DIM],  g_al[MTOT * DIM];

__device__ __forceinline__ uint32_t smem_u32(const void* p) {
    uint32_t a;
    asm("{ .reg .u64 t; cvta.to.shared.u64 t, %1; cvt.u32.u64 %0, t; }"
        : "=r"(a) : "l"(p));
    return a;
}

// ---------------------------------------------------------------------------
// fp32 -> fp16 hi/lo split
// ---------------------------------------------------------------------------
__global__ __launch_bounds__(256)
void split_kernel(const float* __restrict__ src, __half* __restrict__ hi,
                  __half* __restrict__ lo, int n4)
{
    int i = blockIdx.x * blockDim.x + threadIdx.x;
    if (i >= n4) return;
    float4 v = ((const float4*)src)[i];
    float vs[4] = {v.x, v.y, v.z, v.w};
    __half h[4], l[4];
#pragma unroll
    for (int j = 0; j < 4; j++) {
        h[j] = __float2half(vs[j]);
        l[j] = __float2half(vs[j] - __half2float(h[j]));
    }
    __half2* hp = (__half2*)(hi + i * 4);
    __half2* lp = (__half2*)(lo + i * 4);
    hp[0] = __half2(h[0], h[1]); hp[1] = __half2(h[2], h[3]);
    lp[0] = __half2(l[0], l[1]); lp[1] = __half2(l[2], l[3]);
}

// ---------------------------------------------------------------------------
// HMMA fp16x3 GEMM: D[M,N] = A[M,K] @ B[N,K]^T  (fp32-accurate)
// CTA 128x128, 8 warps (2m x 4n), warp tile 64x32, K-chunk 64,
// cp.async double-buffered SMEM, SW128 xor swizzle, ldmatrix fragments.
// mode 0: scatter into g_q/g_k/g_v ([B,H,N,D])   mode 1: OUT = D + bias
// ---------------------------------------------------------------------------
#define KC          64
#define NKC         (DIM / KC)                 // 12
#define TILE_B      (128 * 128)                // 128 rows x 128B (64 halfs)
#define STAGE_B     (4 * TILE_B)               // Ah, Al, Bh, Bl
#define GEMM_SMEM   (2 * STAGE_B)              // 131072

#define SWZ(off) ((off) ^ (((off) >> 3) & 0x70))

__device__ __forceinline__ void cp_tile(uint32_t dst, const __half* g, int tid)
{
#pragma unroll
    for (int i = 0; i < 4; i++) {
        const int p = tid + i * 256;           // 0..1023
        const int r = p >> 3;
        const int c = p & 7;
        const uint32_t off = (uint32_t)(r * 128 + c * 16);
        const void* src = (const char*)(g + (size_t)r * DIM) + c * 16;
        asm volatile("cp.async.cg.shared.global [%0], [%1], 16;"
                     :: "r"(dst + SWZ(off)), "l"(src) : "memory");
    }
}

#define LDSM_X4(r0, r1, r2, r3, addr) \
    asm volatile("ldmatrix.sync.aligned.m8n8.x4.shared.b16 {%0,%1,%2,%3}, [%4];" \
        : "=r"(r0), "=r"(r1), "=r"(r2), "=r"(r3) : "r"(addr))

__device__ __forceinline__ void mma16816(float* c, const uint32_t* a,
                                         const uint32_t* b)
{
    asm volatile("mma.sync.aligned.m16n8k16.row.col.f32.f16.f16.f32 "
        "{%0,%1,%2,%3}, {%4,%5,%6,%7}, {%8,%9}, {%0,%1,%2,%3};"
        : "+f"(c[0]), "+f"(c[1]), "+f"(c[2]), "+f"(c[3])
        : "r"(a[0]), "r"(a[1]), "r"(a[2]), "r"(a[3]), "r"(b[0]), "r"(b[1]));
}

__global__ __launch_bounds__(256, 1)
void hmma_gemm_kernel(const __half* __restrict__ Ah, const __half* __restrict__ Al,
                      const __half* __restrict__ Bh, const __half* __restrict__ Bl,
                      const float* __restrict__ bias, float* __restrict__ OUT,
                      int mode)
{
    extern __shared__ char smem[];
    const uint32_t sbase = smem_u32(smem);
    const int tid  = threadIdx.x;
    const int wid  = tid >> 5;
    const int lane = tid & 31;
    const int wm   = wid >> 2;          // 0..1
    const int wn   = wid & 3;           // 0..3
    const int n0   = blockIdx.x * 128;
    const int m0   = blockIdx.y * 128;

    const __half* Ah0 = Ah + (size_t)m0 * DIM;
    const __half* Al0 = Al + (size_t)m0 * DIM;
    const __half* Bh0 = Bh + (size_t)n0 * DIM;
    const __half* Bl0 = Bl + (size_t)n0 * DIM;

    float acc[4][4][4];
#pragma unroll
    for (int i = 0; i < 4; i++)
#pragma unroll
        for (int j = 0; j < 4; j++)
#pragma unroll
            for (int k = 0; k < 4; k++) acc[i][j][k] = 0.f;

    // prologue: stage 0
    {
        const uint32_t st = sbase;
        cp_tile(st,              Ah0, tid);
        cp_tile(st + TILE_B,     Al0, tid);
        cp_tile(st + 2 * TILE_B, Bh0, tid);
        cp_tile(st + 3 * TILE_B, Bl0, tid);
        asm volatile("cp.async.commit_group;" ::: "memory");
    }

    // per-lane ldmatrix address components (within a tile, pre-swizzle row part)
    const int a_row = wm * 64 + (lane & 15);          // + mf*16
    const int a_kh  = (lane >> 4) * 16;               // byte offset in row
    const int b_row = wn * 32 + (lane & 7) + ((lane >> 4) << 3);  // + nfp*16
    const int b_kh  = ((lane >> 3) & 1) * 16;

    for (int kc = 0; kc < NKC; kc++) {
        if (kc + 1 < NKC) {
            const uint32_t st = sbase + ((kc + 1) & 1) * STAGE_B;
            const int koff = (kc + 1) * KC;
            cp_tile(st,              Ah0 + koff, tid);
            cp_tile(st + TILE_B,     Al0 + koff, tid);
            cp_tile(st + 2 * TILE_B, Bh0 + koff, tid);
            cp_tile(st + 3 * TILE_B, Bl0 + koff, tid);
            asm volatile("cp.async.commit_group;" ::: "memory");
            asm volatile("cp.async.wait_group 1;" ::: "memory");
        } else {
            asm volatile("cp.async.wait_group 0;" ::: "memory");
        }
        __syncthreads();

        const uint32_t st = sbase + (kc & 1) * STAGE_B;
        const uint32_t sAh = st, sAl = st + TILE_B;
        const uint32_t sBh = st + 2 * TILE_B, sBl = st + 3 * TILE_B;

#pragma unroll
        for (int ks = 0; ks < KC / 16; ks++) {
            uint32_t ah[4][4], al[4][4], bh[2][4], bl[2][4];
#pragma unroll
            for (int mf = 0; mf < 4; mf++) {
                uint32_t off = (uint32_t)((a_row + mf * 16) * 128 + ks * 32 + a_kh);
                LDSM_X4(ah[mf][0], ah[mf][1], ah[mf][2], ah[mf][3], sAh + SWZ(off));
                LDSM_X4(al[mf][0], al[mf][1], al[mf][2], al[mf][3], sAl + SWZ(off));
            }
#pragma unroll
            for (int nfp = 0; nfp < 2; nfp++) {
                uint32_t off = (uint32_t)((b_row + nfp * 16) * 128 + ks * 32 + b_kh);
                LDSM_X4(bh[nfp][0], bh[nfp][1], bh[nfp][2], bh[nfp][3], sBh + SWZ(off));
                LDSM_X4(bl[nfp][0], bl[nfp][1], bl[nfp][2], bl[nfp][3], sBl + SWZ(off));
            }
#pragma unroll
            for (int mf = 0; mf < 4; mf++)
#pragma unroll
                for (int nf = 0; nf < 4; nf++) {
                    const uint32_t* Bhf = &bh[nf >> 1][(nf & 1) * 2];
                    const uint32_t* Blf = &bl[nf >> 1][(nf & 1) * 2];
                    mma16816(acc[mf][nf], ah[mf], Bhf);
                    mma16816(acc[mf][nf], al[mf], Bhf);
                    mma16816(acc[mf][nf], ah[mf], Blf);
                }
        }
        __syncthreads();
    }

    // epilogue: c0,c1 at (row, col), c2,c3 at (row+8, col)
    const int rbase = m0 + wm * 64 + (lane >> 2);
    const int cbase = n0 + wn * 32 + (lane & 3) * 2;

    if (mode == 0) {
#pragma unroll
        for (int nf = 0; nf < 4; nf++) {
            const int gc  = cbase + nf * 8;
            const int sel = gc / DIM;
            const int h   = (gc % DIM) >> 6;
            const int d   = gc & 63;
            float* dst = sel == 0 ? g_q : (sel == 1 ? g_k : g_v);
#pragma unroll
            for (int mf = 0; mf < 4; mf++) {
#pragma unroll
                for (int rr = 0; rr < 2; rr++) {
                    const int m = rbase + mf * 16 + rr * 8;
                    const int b = m >> 10;
                    const int n = m & 1023;
                    float* p = dst + ((size_t)((b * NHEADS + h) * SEQ + n)) * HDIM + d;
                    *(float2*)p = make_float2(acc[mf][nf][rr * 2],
                                              acc[mf][nf][rr * 2 + 1]);
                }
            }
        }
    } else {
#pragma unroll
        for (int nf = 0; nf < 4; nf++) {
            const int gc = cbase + nf * 8;
            const float2 bv = *(const float2*)(bias + gc);
#pragma unroll
            for (int mf = 0; mf < 4; mf++) {
#pragma unroll
                for (int rr = 0; rr < 2; rr++) {
                    const int m = rbase + mf * 16 + rr * 8;
                    float* p = OUT + (size_t)m * DIM + gc;
                    *(float2*)p = make_float2(acc[mf][nf][rr * 2] + bv.x,
                                              acc[mf][nf][rr * 2 + 1] + bv.y);
                }
            }
        }
    }
}

// ---------------------------------------------------------------------------
// Fused flash-style fp32 attention; epilogue emits fp16 hi/lo for proj GEMM
// ---------------------------------------------------------------------------
#define QS_STRIDE 132
#define VS_STRIDE 68
#define SS_STRIDE 129

#define SM_QS   0
#define SM_KS   (64 * QS_STRIDE)
#define SM_VS   (SM_KS + 64 * QS_STRIDE)
#define SM_SS   (SM_VS + 128 * VS_STRIDE)
#define SM_FAC  (SM_SS + 128 * SS_STRIDE)
#define SM_MROW (SM_FAC + 128)
#define SM_LROW (SM_MROW + 128)
#define SMEM_FLOATS (SM_LROW + 128)
#define ATTN_SMEM_BYTES (SMEM_FLOATS * 4)

__global__ __launch_bounds__(256, 1)
void attn_kernel()
{
    extern __shared__ float sm[];
    float* Qs   = sm + SM_QS;
    float* Ks   = sm + SM_KS;
    float* Vs   = sm + SM_VS;
    float* Ss   = sm + SM_SS;
    float* facs = sm + SM_FAC;
    float* mrow = sm + SM_MROW;
    float* lrow = sm + SM_LROW;

    const int tid = threadIdx.x;
    const int bh  = blockIdx.x;
    const int qt  = blockIdx.y;
    const float* Qg = g_q + (size_t)bh * SEQ * HDIM + (size_t)qt * 128 * HDIM;
    const float* Kg = g_k + (size_t)bh * SEQ * HDIM;
    const float* Vg = g_v + (size_t)bh * SEQ * HDIM;

    for (int p = tid; p < 128 * 16; p += 256) {
        const int r  = p >> 4;
        const int c4 = (p & 15) << 2;
        float4 qv = *(const float4*)(Qg + (size_t)r * HDIM + c4);
        Qs[(c4 + 0) * QS_STRIDE + r] = qv.x;
        Qs[(c4 + 1) * QS_STRIDE + r] = qv.y;
        Qs[(c4 + 2) * QS_STRIDE + r] = qv.z;
        Qs[(c4 + 3) * QS_STRIDE + r] = qv.w;
    }
    if (tid < 128) { mrow[tid] = -1e30f; lrow[tid] = 0.f; }

    const int ty = tid >> 4;
    const int tx = tid & 15;
    float o[8][4];
#pragma unroll
    for (int i = 0; i < 8; i++)
#pragma unroll
        for (int j = 0; j < 4; j++) o[i][j] = 0.f;

    for (int j0 = 0; j0 < SEQ; j0 += 128) {
        __syncthreads();
        for (int p = tid; p < 128 * 16; p += 256) {
            const int r  = p >> 4;
            const int c4 = (p & 15) << 2;
            float4 kv = *(const float4*)(Kg + (size_t)(j0 + r) * HDIM + c4);
            Ks[(c4 + 0) * QS_STRIDE + r] = kv.x;
            Ks[(c4 + 1) * QS_STRIDE + r] = kv.y;
            Ks[(c4 + 2) * QS_STRIDE + r] = kv.z;
            Ks[(c4 + 3) * QS_STRIDE + r] = kv.w;
            float4 vv = *(const float4*)(Vg + (size_t)(j0 + r) * HDIM + c4);
            *(float4*)&Vs[r * VS_STRIDE + c4] = vv;
        }
        __syncthreads();

        float s[8][8];
#pragma unroll
        for (int i = 0; i < 8; i++)
#pragma unroll
            for (int j = 0; j < 8; j++) s[i][j] = 0.f;
#pragma unroll 8
        for (int d = 0; d < HDIM; d++) {
            float a[8], b[8];
            *(float4*)&a[0] = *(const float4*)&Qs[d * QS_STRIDE + ty * 8];
            *(float4*)&a[4] = *(const float4*)&Qs[d * QS_STRIDE + ty * 8 + 4];
            *(float4*)&b[0] = *(const float4*)&Ks[d * QS_STRIDE + tx * 8];
            *(float4*)&b[4] = *(const float4*)&Ks[d * QS_STRIDE + tx * 8 + 4];
#pragma unroll
            for (int i = 0; i < 8; i++)
#pragma unroll
                for (int j = 0; j < 8; j++)
                    s[i][j] += a[i] * b[j];
        }
#pragma unroll
        for (int i = 0; i < 8; i++)
#pragma unroll
            for (int j = 0; j < 8; j++)
                Ss[(ty * 8 + i) * SS_STRIDE + tx * 8 + j] = s[i][j] * ATT_SCALE;
        __syncthreads();

        if (tid < 128) {
            float* row = &Ss[tid * SS_STRIDE];
            const float mold = mrow[tid];
            float mx = mold;
#pragma unroll 8
            for (int c = 0; c < 128; c++) mx = fmaxf(mx, row[c]);
            const float fac = __expf(mold - mx);
            float sum = 0.f;
#pragma unroll 8
            for (int c = 0; c < 128; c++) {
                const float e = __expf(row[c] - mx);
                row[c] = e;
                sum += e;
            }
            lrow[tid] = lrow[tid] * fac + sum;
            mrow[tid] = mx;
            facs[tid] = fac;
        }
        __syncthreads();

        float f[8];
#pragma unroll
        for (int i = 0; i < 8; i++) f[i] = facs[ty * 8 + i];
#pragma unroll
        for (int i = 0; i < 8; i++)
#pragma unroll
            for (int j = 0; j < 4; j++) o[i][j] *= f[i];

#pragma unroll 4
        for (int kc = 0; kc < 128; kc++) {
            float4 vv = *(const float4*)&Vs[kc * VS_STRIDE + tx * 4];
            float p[8];
#pragma unroll
            for (int i = 0; i < 8; i++) p[i] = Ss[(ty * 8 + i) * SS_STRIDE + kc];
#pragma unroll
            for (int i = 0; i < 8; i++) {
                o[i][0] += p[i] * vv.x;
                o[i][1] += p[i] * vv.y;
                o[i][2] += p[i] * vv.z;
                o[i][3] += p[i] * vv.w;
            }
        }
    }

    // Epilogue: normalize, split into fp16 hi/lo for the proj HMMA GEMM
    const int h = bh % NHEADS;
    const int b = bh / NHEADS;
#pragma unroll
    for (int i = 0; i < 8; i++) {
        const float linv = 1.f / lrow[ty * 8 + i];
        const int n = qt * 128 + ty * 8 + i;
        const size_t base = ((size_t)(b * SEQ + n)) * DIM + h * HDIM + tx * 4;
        __half hh[4], ll[4];
#pragma unroll
        for (int j = 0; j < 4; j++) {
            const float v = o[i][j] * linv;
            hh[j] = __float2half(v);
            ll[j] = __float2half(v - __half2float(hh[j]));
        }
        *(__half2*)(g_ah + base)     = __half2(hh[0], hh[1]);
        *(__half2*)(g_ah + base + 2) = __half2(hh[2], hh[3]);
        *(__half2*)(g_al + base)     = __half2(ll[0], ll[1]);
        *(__half2*)(g_al + base + 2) = __half2(ll[2], ll[3]);
    }
}

// ---------------------------------------------------------------------------
extern "C" void kernel_launch(void* const* d_in, const int* in_sizes, int n_in,
                              void* d_out, int out_size)
{
    (void)in_sizes; (void)n_in; (void)out_size;
    const float* x      = (const float*)d_in[0];
    const float* w_qkv  = (const float*)d_in[1];
    const float* w_proj = (const float*)d_in[2];
    const float* b_proj = (const float*)d_in[3];
    float* out = (float*)d_out;

    cudaFuncSetAttribute(attn_kernel, cudaFuncAttributeMaxDynamicSharedMemorySize,
                         ATTN_SMEM_BYTES);
    cudaFuncSetAttribute(hmma_gemm_kernel, cudaFuncAttributeMaxDynamicSharedMemorySize,
                         GEMM_SMEM);

    __half *xh, *xl, *wqh, *wql, *wph, *wpl, *ah, *al;
    cudaGetSymbolAddress((void**)&xh,  g_xh);  cudaGetSymbolAddress((void**)&xl,  g_xl);
    cudaGetSymbolAddress((void**)&wqh, g_wqh); cudaGetSymbolAddress((void**)&wql, g_wql);
    cudaGetSymbolAddress((void**)&wph, g_wph); cudaGetSymbolAddress((void**)&wpl, g_wpl);
    cudaGetSymbolAddress((void**)&ah,  g_ah);  cudaGetSymbolAddress((void**)&al,  g_al);

    // 1. hi/lo splits
    split_kernel<<<(MTOT * DIM / 4 + 255) / 256, 256>>>(x, xh, xl, MTOT * DIM / 4);
    split_kernel<<<(QKVN * DIM / 4 + 255) / 256, 256>>>(w_qkv, wqh, wql, QKVN * DIM / 4);
    split_kernel<<<(DIM * DIM / 4 + 255) / 256, 256>>>(w_proj, wph, wpl, DIM * DIM / 4);

    // 2. QKV GEMM (HMMA fp16x3) -> g_q/g_k/g_v
    hmma_gemm_kernel<<<dim3(QKVN / 128, MTOT / 128), 256, GEMM_SMEM>>>(
        xh, xl, wqh, wql, nullptr, nullptr, 0);

    // 3. attention (fp32) -> g_ah/g_al
    attn_kernel<<<dim3(BATCH * NHEADS, SEQ / 128), 256, ATTN_SMEM_BYTES>>>();

    // 4. output projection (HMMA fp16x3) -> out
    hmma_gemm_kernel<<<dim3(DIM / 128, MTOT / 128), 256, GEMM_SMEM>>>(
        ah, al, wph, wpl, b_proj, out, 1);
}

// round 4
// speedup vs baseline: 3.2013x; 2.0395x over previous
#include <cuda_runtime.h>
#include <cuda_fp16.h>
#include <cstdint>

#define DIM     768
#define NHEADS  12
#define HDIM    64
#define BATCH   8
#define SEQ     1024
#define MTOT    (BATCH * SEQ)      // 8192
#define QKVN    (3 * DIM)          // 2304
#define ATT_SCALE 0.125f

// ---------------------------------------------------------------------------
// Scratch (__device__ globals; no allocations allowed)
// ---------------------------------------------------------------------------
__device__ __half g_qh[BATCH * NHEADS * SEQ * HDIM], g_ql[BATCH * NHEADS * SEQ * HDIM];
__device__ __half g_kh[BATCH * NHEADS * SEQ * HDIM], g_kl[BATCH * NHEADS * SEQ * HDIM];
__device__ __half g_vh[BATCH * NHEADS * HDIM * SEQ], g_vl[BATCH * NHEADS * HDIM * SEQ]; // [B,H,D,N]
__device__ __half g_xh[MTOT * DIM], g_xl[MTOT * DIM];
__device__ __half g_wqh[QKVN * DIM], g_wql[QKVN * DIM];
__device__ __half g_wph[DIM * DIM],  g_wpl[DIM * DIM];
__device__ __half g_ah[MTOT * DIM],  g_al[MTOT * DIM];

__device__ __forceinline__ uint32_t smem_u32(const void* p) {
    uint32_t a;
    asm("{ .reg .u64 t; cvta.to.shared.u64 t, %1; cvt.u32.u64 %0, t; }"
        : "=r"(a) : "l"(p));
    return a;
}

#define SWZ(off) ((off) ^ (((off) >> 3) & 0x70))

#define LDSM_X4(r0, r1, r2, r3, addr) \
    asm volatile("ldmatrix.sync.aligned.m8n8.x4.shared.b16 {%0,%1,%2,%3}, [%4];" \
        : "=r"(r0), "=r"(r1), "=r"(r2), "=r"(r3) : "r"(addr))

__device__ __forceinline__ void mma16816(float* c, const uint32_t* a,
                                         const uint32_t* b)
{
    asm volatile("mma.sync.aligned.m16n8k16.row.col.f32.f16.f16.f32 "
        "{%0,%1,%2,%3}, {%4,%5,%6,%7}, {%8,%9}, {%0,%1,%2,%3};"
        : "+f"(c[0]), "+f"(c[1]), "+f"(c[2]), "+f"(c[3])
        : "r"(a[0]), "r"(a[1]), "r"(a[2]), "r"(a[3]), "r"(b[0]), "r"(b[1]));
}

__device__ __forceinline__ uint32_t packh2(__half x, __half y) {
    __half2 t = __half2(x, y);
    return *(uint32_t*)&t;
}
// split (x,y) into fp16 hi and lo half2 register pairs
__device__ __forceinline__ void split2(float x, float y, uint32_t& hi, uint32_t& lo) {
    __half hx = __float2half(x), hy = __float2half(y);
    hi = packh2(hx, hy);
    lo = packh2(__float2half(x - __half2float(hx)),
                __float2half(y - __half2float(hy)));
}

// ---------------------------------------------------------------------------
// fp32 -> fp16 hi/lo split
// ---------------------------------------------------------------------------
__global__ __launch_bounds__(256)
void split_kernel(const float* __restrict__ src, __half* __restrict__ hi,
                  __half* __restrict__ lo, int n4)
{
    int i = blockIdx.x * blockDim.x + threadIdx.x;
    if (i >= n4) return;
    float4 v = ((const float4*)src)[i];
    float vs[4] = {v.x, v.y, v.z, v.w};
    __half h[4], l[4];
#pragma unroll
    for (int j = 0; j < 4; j++) {
        h[j] = __float2half(vs[j]);
        l[j] = __float2half(vs[j] - __half2float(h[j]));
    }
    __half2* hp = (__half2*)(hi + i * 4);
    __half2* lp = (__half2*)(lo + i * 4);
    hp[0] = __half2(h[0], h[1]); hp[1] = __half2(h[2], h[3]);
    lp[0] = __half2(l[0], l[1]); lp[1] = __half2(l[2], l[3]);
}

// ---------------------------------------------------------------------------
// HMMA fp16x3 GEMM: D[M,N] = A[M,K] @ B[N,K]^T
// mode 0: split-scatter q/k/v as fp16 hi/lo (Q scaled, V transposed)
// mode 1: OUT = D + bias (fp32)
// ---------------------------------------------------------------------------
#define KC          64
#define NKC         (DIM / KC)                 // 12
#define TILE_B      (128 * 128)
#define STAGE_B     (4 * TILE_B)
#define GEMM_SMEM   (2 * STAGE_B)              // 131072

__device__ __forceinline__ void cp_tile(uint32_t dst, const __half* g, int tid)
{
#pragma unroll
    for (int i = 0; i < 4; i++) {
        const int p = tid + i * 256;
        const int r = p >> 3;
        const int c = p & 7;
        const uint32_t off = (uint32_t)(r * 128 + c * 16);
        const void* src = (const char*)(g + (size_t)r * DIM) + c * 16;
        asm volatile("cp.async.cg.shared.global [%0], [%1], 16;"
                     :: "r"(dst + SWZ(off)), "l"(src) : "memory");
    }
}

__global__ __launch_bounds__(256, 1)
void hmma_gemm_kernel(const __half* __restrict__ Ah, const __half* __restrict__ Al,
                      const __half* __restrict__ Bh, const __half* __restrict__ Bl,
                      const float* __restrict__ bias, float* __restrict__ OUT,
                      int mode)
{
    extern __shared__ char smem[];
    const uint32_t sbase = smem_u32(smem);
    const int tid  = threadIdx.x;
    const int wid  = tid >> 5;
    const int lane = tid & 31;
    const int wm   = wid >> 2;
    const int wn   = wid & 3;
    const int n0   = blockIdx.x * 128;
    const int m0   = blockIdx.y * 128;

    const __half* Ah0 = Ah + (size_t)m0 * DIM;
    const __half* Al0 = Al + (size_t)m0 * DIM;
    const __half* Bh0 = Bh + (size_t)n0 * DIM;
    const __half* Bl0 = Bl + (size_t)n0 * DIM;

    float acc[4][4][4];
#pragma unroll
    for (int i = 0; i < 4; i++)
#pragma unroll
        for (int j = 0; j < 4; j++)
#pragma unroll
            for (int k = 0; k < 4; k++) acc[i][j][k] = 0.f;

    {
        const uint32_t st = sbase;
        cp_tile(st,              Ah0, tid);
        cp_tile(st + TILE_B,     Al0, tid);
        cp_tile(st + 2 * TILE_B, Bh0, tid);
        cp_tile(st + 3 * TILE_B, Bl0, tid);
        asm volatile("cp.async.commit_group;" ::: "memory");
    }

    const int a_row = wm * 64 + (lane & 15);
    const int a_kh  = (lane >> 4) * 16;
    const int b_row = wn * 32 + (lane & 7) + ((lane >> 4) << 3);
    const int b_kh  = ((lane >> 3) & 1) * 16;

    for (int kc = 0; kc < NKC; kc++) {
        if (kc + 1 < NKC) {
            const uint32_t st = sbase + ((kc + 1) & 1) * STAGE_B;
            const int koff = (kc + 1) * KC;
            cp_tile(st,              Ah0 + koff, tid);
            cp_tile(st + TILE_B,     Al0 + koff, tid);
            cp_tile(st + 2 * TILE_B, Bh0 + koff, tid);
            cp_tile(st + 3 * TILE_B, Bl0 + koff, tid);
            asm volatile("cp.async.commit_group;" ::: "memory");
            asm volatile("cp.async.wait_group 1;" ::: "memory");
        } else {
            asm volatile("cp.async.wait_group 0;" ::: "memory");
        }
        __syncthreads();

        const uint32_t st = sbase + (kc & 1) * STAGE_B;
        const uint32_t sAh = st, sAl = st + TILE_B;
        const uint32_t sBh = st + 2 * TILE_B, sBl = st + 3 * TILE_B;

#pragma unroll
        for (int ks = 0; ks < KC / 16; ks++) {
            uint32_t ah[4][4], al[4][4], bh[2][4], bl[2][4];
#pragma unroll
            for (int mf = 0; mf < 4; mf++) {
                uint32_t off = (uint32_t)((a_row + mf * 16) * 128 + ks * 32 + a_kh);
                LDSM_X4(ah[mf][0], ah[mf][1], ah[mf][2], ah[mf][3], sAh + SWZ(off));
                LDSM_X4(al[mf][0], al[mf][1], al[mf][2], al[mf][3], sAl + SWZ(off));
            }
#pragma unroll
            for (int nfp = 0; nfp < 2; nfp++) {
                uint32_t off = (uint32_t)((b_row + nfp * 16) * 128 + ks * 32 + b_kh);
                LDSM_X4(bh[nfp][0], bh[nfp][1], bh[nfp][2], bh[nfp][3], sBh + SWZ(off));
                LDSM_X4(bl[nfp][0], bl[nfp][1], bl[nfp][2], bl[nfp][3], sBl + SWZ(off));
            }
#pragma unroll
            for (int mf = 0; mf < 4; mf++)
#pragma unroll
                for (int nf = 0; nf < 4; nf++) {
                    const uint32_t* Bhf = &bh[nf >> 1][(nf & 1) * 2];
                    const uint32_t* Blf = &bl[nf >> 1][(nf & 1) * 2];
                    mma16816(acc[mf][nf], ah[mf], Bhf);
                    mma16816(acc[mf][nf], al[mf], Bhf);
                    mma16816(acc[mf][nf], ah[mf], Blf);
                }
        }
        __syncthreads();
    }

    const int rbase = m0 + wm * 64 + (lane >> 2);
    const int cbase = n0 + wn * 32 + (lane & 3) * 2;

    if (mode == 0) {
#pragma unroll
        for (int nf = 0; nf < 4; nf++) {
            const int gc  = cbase + nf * 8;
            const int sel = gc / DIM;
            const int rem = gc % DIM;
            const int h   = rem >> 6;
            const int d   = rem & 63;
#pragma unroll
            for (int mf = 0; mf < 4; mf++) {
#pragma unroll
                for (int rr = 0; rr < 2; rr++) {
                    const int m = rbase + mf * 16 + rr * 8;
                    const int b = m >> 10;
                    const int n = m & 1023;
                    float v0 = acc[mf][nf][rr * 2];
                    float v1 = acc[mf][nf][rr * 2 + 1];
                    if (sel == 0) { v0 *= ATT_SCALE; v1 *= ATT_SCALE; }
                    __half h0 = __float2half(v0), h1 = __float2half(v1);
                    __half l0 = __float2half(v0 - __half2float(h0));
                    __half l1 = __float2half(v1 - __half2float(h1));
                    if (sel < 2) {
                        const size_t a = ((size_t)((b * NHEADS + h) * SEQ + n)) * HDIM + d;
                        __half* Hp = sel ? g_kh : g_qh;
                        __half* Lp = sel ? g_kl : g_ql;
                        *(__half2*)(Hp + a) = __half2(h0, h1);
                        *(__half2*)(Lp + a) = __half2(l0, l1);
                    } else {
                        const size_t a = ((size_t)((b * NHEADS + h) * HDIM + d)) * SEQ + n;
                        g_vh[a] = h0; g_vh[a + SEQ] = h1;
                        g_vl[a] = l0; g_vl[a + SEQ] = l1;
                    }
                }
            }
        }
    } else {
#pragma unroll
        for (int nf = 0; nf < 4; nf++) {
            const int gc = cbase + nf * 8;
            const float2 bv = *(const float2*)(bias + gc);
#pragma unroll
            for (int mf = 0; mf < 4; mf++) {
#pragma unroll
                for (int rr = 0; rr < 2; rr++) {
                    const int m = rbase + mf * 16 + rr * 8;
                    float* p = OUT + (size_t)m * DIM + gc;
                    *(float2*)p = make_float2(acc[mf][nf][rr * 2] + bv.x,
                                              acc[mf][nf][rr * 2 + 1] + bv.y);
                }
            }
        }
    }
}

// ---------------------------------------------------------------------------
// HMMA fp16x3 flash attention. CTA = (bh, 128-query tile), 8 warps,
// warp tile = 16 rows x 128 cols (full-width -> in-warp softmax reductions).
// Q frags persistent in registers; K/V double-buffered via cp.async.
// ---------------------------------------------------------------------------
#define AT_QH     0
#define AT_QL     16384
#define AT_STAGE0 32768
#define AT_STAGEB 65536                     // Kh,Kl,Vh,Vl 16KB each
#define AT_SMEM   (AT_STAGE0 + 2 * AT_STAGEB)   // 163840

// contiguous 128x64-half tile (rows of 128B) -> swizzled SMEM
__device__ __forceinline__ void cp_kq(uint32_t dst, const __half* g, int tid)
{
#pragma unroll
    for (int i = 0; i < 4; i++) {
        const int p = tid + i * 256;
        const int r = p >> 3;
        const int c = p & 7;
        const uint32_t off = (uint32_t)(r * 128 + c * 16);
        const void* src = (const char*)(g + (size_t)r * 64) + c * 16;
        asm volatile("cp.async.cg.shared.global [%0], [%1], 16;"
                     :: "r"(dst + SWZ(off)), "l"(src) : "memory");
    }
}
// V^T tile: 64 d-rows x 128 seq cols, stored as 2 planes of [64][64 halves]
__device__ __forceinline__ void cp_v(uint32_t dst, const __half* g, int j0, int tid)
{
#pragma unroll
    for (int i = 0; i < 4; i++) {
        const int p = tid + i * 256;
        const int plane = p >> 9;
        const int rem = p & 511;
        const int d = rem >> 3;
        const int c = rem & 7;
        const void* src = g + (size_t)d * SEQ + j0 + plane * 64 + c * 8;
        const uint32_t off = (uint32_t)(d * 128 + c * 16);
        asm volatile("cp.async.cg.shared.global [%0], [%1], 16;"
                     :: "r"(dst + plane * 8192 + SWZ(off)), "l"(src) : "memory");
    }
}

__global__ __launch_bounds__(256, 1)
void attn_hmma_kernel()
{
    extern __shared__ char smem[];
    const uint32_t sb = smem_u32(smem);
    const int tid = threadIdx.x, wid = tid >> 5, lane = tid & 31;
    const int bh = blockIdx.x, qt = blockIdx.y;

    const __half* qhg = g_qh + ((size_t)bh * SEQ + qt * 128) * HDIM;
    const __half* qlg = g_ql + ((size_t)bh * SEQ + qt * 128) * HDIM;
    const __half* khg = g_kh + (size_t)bh * SEQ * HDIM;
    const __half* klg = g_kl + (size_t)bh * SEQ * HDIM;
    const __half* vhg = g_vh + (size_t)bh * HDIM * SEQ;
    const __half* vlg = g_vl + (size_t)bh * HDIM * SEQ;

    // prologue: Q + stage 0 (group 0), stage 1 (group 1)
    cp_kq(sb + AT_QH, qhg, tid);
    cp_kq(sb + AT_QL, qlg, tid);
    {
        const uint32_t st = sb + AT_STAGE0;
        cp_kq(st,         khg, tid);
        cp_kq(st + 16384, klg, tid);
        cp_v (st + 32768, vhg, 0, tid);
        cp_v (st + 49152, vlg, 0, tid);
        asm volatile("cp.async.commit_group;" ::: "memory");
    }
    {
        const uint32_t st = sb + AT_STAGE0 + AT_STAGEB;
        cp_kq(st,         khg + 128 * HDIM, tid);
        cp_kq(st + 16384, klg + 128 * HDIM, tid);
        cp_v (st + 32768, vhg, 128, tid);
        cp_v (st + 49152, vlg, 128, tid);
        asm volatile("cp.async.commit_group;" ::: "memory");
    }

    float m0 = -1e30f, m1 = -1e30f, l0 = 0.f, l1 = 0.f;
    float oacc[8][4];
#pragma unroll
    for (int i = 0; i < 8; i++)
#pragma unroll
        for (int j = 0; j < 4; j++) oacc[i][j] = 0.f;

    uint32_t qfh[4][4], qfl[4][4];
    const int brow = (lane & 7) + ((lane >> 4) << 3);
    const int bkh  = ((lane >> 3) & 1) * 16;

    for (int j = 0; j < 8; j++) {
        if (j < 7) asm volatile("cp.async.wait_group 1;" ::: "memory");
        else       asm volatile("cp.async.wait_group 0;" ::: "memory");
        __syncthreads();

        if (j == 0) {
            const int a_row = wid * 16 + (lane & 15);
            const int a_kh  = (lane >> 4) * 16;
#pragma unroll
            for (int ks = 0; ks < 4; ks++) {
                uint32_t off = (uint32_t)(a_row * 128 + ks * 32 + a_kh);
                LDSM_X4(qfh[ks][0], qfh[ks][1], qfh[ks][2], qfh[ks][3],
                        sb + AT_QH + SWZ(off));
                LDSM_X4(qfl[ks][0], qfl[ks][1], qfl[ks][2], qfl[ks][3],
                        sb + AT_QL + SWZ(off));
            }
        }

        const uint32_t st  = sb + AT_STAGE0 + (j & 1) * AT_STAGEB;
        const uint32_t sKH = st, sKL = st + 16384;
        const uint32_t sVH = st + 32768, sVL = st + 49152;

        // ---- S = Qs @ K^T (scale folded into Q) ----
        float sacc[16][4];
#pragma unroll
        for (int i = 0; i < 16; i++)
#pragma unroll
            for (int k = 0; k < 4; k++) sacc[i][k] = 0.f;

#pragma unroll
        for (int ks = 0; ks < 4; ks++) {
#pragma unroll
            for (int nfp = 0; nfp < 8; nfp++) {
                uint32_t kh[4], kl[4];
                uint32_t off = (uint32_t)((nfp * 16 + brow) * 128 + ks * 32 + bkh);
                LDSM_X4(kh[0], kh[1], kh[2], kh[3], sKH + SWZ(off));
                LDSM_X4(kl[0], kl[1], kl[2], kl[3], sKL + SWZ(off));
                mma16816(sacc[2 * nfp],     qfh[ks], kh);
                mma16816(sacc[2 * nfp + 1], qfh[ks], kh + 2);
                mma16816(sacc[2 * nfp],     qfl[ks], kh);
                mma16816(sacc[2 * nfp + 1], qfl[ks], kh + 2);
                mma16816(sacc[2 * nfp],     qfh[ks], kl);
                mma16816(sacc[2 * nfp + 1], qfh[ks], kl + 2);
            }
        }

        // ---- online softmax (in-warp; rows r0 = lane/4, r1 = lane/4+8) ----
        float mx0 = m0, mx1 = m1;
#pragma unroll
        for (int nf = 0; nf < 16; nf++) {
            mx0 = fmaxf(mx0, fmaxf(sacc[nf][0], sacc[nf][1]));
            mx1 = fmaxf(mx1, fmaxf(sacc[nf][2], sacc[nf][3]));
        }
        mx0 = fmaxf(mx0, __shfl_xor_sync(0xffffffff, mx0, 1));
        mx0 = fmaxf(mx0, __shfl_xor_sync(0xffffffff, mx0, 2));
        mx1 = fmaxf(mx1, __shfl_xor_sync(0xffffffff, mx1, 1));
        mx1 = fmaxf(mx1, __shfl_xor_sync(0xffffffff, mx1, 2));

        const float fac0 = __expf(m0 - mx0);
        const float fac1 = __expf(m1 - mx1);
        float sum0 = 0.f, sum1 = 0.f;
#pragma unroll
        for (int nf = 0; nf < 16; nf++) {
            float e0 = __expf(sacc[nf][0] - mx0); sacc[nf][0] = e0; sum0 += e0;
            float e1 = __expf(sacc[nf][1] - mx0); sacc[nf][1] = e1; sum0 += e1;
            float e2 = __expf(sacc[nf][2] - mx1); sacc[nf][2] = e2; sum1 += e2;
            float e3 = __expf(sacc[nf][3] - mx1); sacc[nf][3] = e3; sum1 += e3;
        }
        sum0 += __shfl_xor_sync(0xffffffff, sum0, 1);
        sum0 += __shfl_xor_sync(0xffffffff, sum0, 2);
        sum1 += __shfl_xor_sync(0xffffffff, sum1, 1);
        sum1 += __shfl_xor_sync(0xffffffff, sum1, 2);
        l0 = l0 * fac0 + sum0; m0 = mx0;
        l1 = l1 * fac1 + sum1; m1 = mx1;

#pragma unroll
        for (int onf = 0; onf < 8; onf++) {
            oacc[onf][0] *= fac0; oacc[onf][1] *= fac0;
            oacc[onf][2] *= fac1; oacc[onf][3] *= fac1;
        }

        // ---- O += P @ V  (P A-frags straight from sacc registers) ----
#pragma unroll
        for (int ks = 0; ks < 8; ks++) {
            uint32_t ah[4], al[4];
            split2(sacc[2 * ks][0],     sacc[2 * ks][1],     ah[0], al[0]);
            split2(sacc[2 * ks][2],     sacc[2 * ks][3],     ah[1], al[1]);
            split2(sacc[2 * ks + 1][0], sacc[2 * ks + 1][1], ah[2], al[2]);
            split2(sacc[2 * ks + 1][2], sacc[2 * ks + 1][3], ah[3], al[3]);
            const uint32_t pb = (ks >> 2) * 8192;
            const int kcol = (ks & 3) * 32;
#pragma unroll
            for (int nfp = 0; nfp < 4; nfp++) {
                uint32_t vh[4], vl[4];
                uint32_t off = (uint32_t)((nfp * 16 + brow) * 128 + kcol + bkh);
                LDSM_X4(vh[0], vh[1], vh[2], vh[3], sVH + pb + SWZ(off));
                LDSM_X4(vl[0], vl[1], vl[2], vl[3], sVL + pb + SWZ(off));
                mma16816(oacc[2 * nfp],     ah, vh);
                mma16816(oacc[2 * nfp + 1], ah, vh + 2);
                mma16816(oacc[2 * nfp],     al, vh);
                mma16816(oacc[2 * nfp + 1], al, vh + 2);
                mma16816(oacc[2 * nfp],     ah, vl);
                mma16816(oacc[2 * nfp + 1], ah, vl + 2);
            }
        }

        __syncthreads();
        if (j + 2 < 8) {
            const uint32_t stn = sb + AT_STAGE0 + (j & 1) * AT_STAGEB;
            const int j0 = (j + 2) * 128;
            cp_kq(stn,         khg + (size_t)j0 * HDIM, tid);
            cp_kq(stn + 16384, klg + (size_t)j0 * HDIM, tid);
            cp_v (stn + 32768, vhg, j0, tid);
            cp_v (stn + 49152, vlg, j0, tid);
            asm volatile("cp.async.commit_group;" ::: "memory");
        }
    }

    // ---- epilogue: normalize, fp16 hi/lo split into g_ah/g_al [B,N,C] ----
    const int h = bh % NHEADS;
    const int b = bh / NHEADS;
    const int n0 = qt * 128 + wid * 16 + (lane >> 2);
    const float li0 = 1.f / l0, li1 = 1.f / l1;
#pragma unroll
    for (int onf = 0; onf < 8; onf++) {
        const int d = onf * 8 + (lane & 3) * 2;
        const size_t base0 = ((size_t)(b * SEQ + n0)) * DIM + h * HDIM + d;
        const size_t base1 = base0 + (size_t)8 * DIM;
        uint32_t hi, lo;
        split2(oacc[onf][0] * li0, oacc[onf][1] * li0, hi, lo);
        *(uint32_t*)(g_ah + base0) = hi;
        *(uint32_t*)(g_al + base0) = lo;
        split2(oacc[onf][2] * li1, oacc[onf][3] * li1, hi, lo);
        *(uint32_t*)(g_ah + base1) = hi;
        *(uint32_t*)(g_al + base1) = lo;
    }
}

// ---------------------------------------------------------------------------
extern "C" void kernel_launch(void* const* d_in, const int* in_sizes, int n_in,
                              void* d_out, int out_size)
{
    (void)in_sizes; (void)n_in; (void)out_size;
    const float* x      = (const float*)d_in[0];
    const float* w_qkv  = (const float*)d_in[1];
    const float* w_proj = (const float*)d_in[2];
    const float* b_proj = (const float*)d_in[3];
    float* out = (float*)d_out;

    cudaFuncSetAttribute(hmma_gemm_kernel, cudaFuncAttributeMaxDynamicSharedMemorySize,
                         GEMM_SMEM);
    cudaFuncSetAttribute(attn_hmma_kernel, cudaFuncAttributeMaxDynamicSharedMemorySize,
                         AT_SMEM);

    __half *xh, *xl, *wqh, *wql, *wph, *wpl, *ah, *al;
    cudaGetSymbolAddress((void**)&xh,  g_xh);  cudaGetSymbolAddress((void**)&xl,  g_xl);
    cudaGetSymbolAddress((void**)&wqh, g_wqh); cudaGetSymbolAddress((void**)&wql, g_wql);
    cudaGetSymbolAddress((void**)&wph, g_wph); cudaGetSymbolAddress((void**)&wpl, g_wpl);
    cudaGetSymbolAddress((void**)&ah,  g_ah);  cudaGetSymbolAddress((void**)&al,  g_al);

    // 1. hi/lo splits
    split_kernel<<<(MTOT * DIM / 4 + 255) / 256, 256>>>(x, xh, xl, MTOT * DIM / 4);
    split_kernel<<<(QKVN * DIM / 4 + 255) / 256, 256>>>(w_qkv, wqh, wql, QKVN * DIM / 4);
    split_kernel<<<(DIM * DIM / 4 + 255) / 256, 256>>>(w_proj, wph, wpl, DIM * DIM / 4);

    // 2. QKV GEMM -> fp16 hi/lo q/k/v (Q scaled, V transposed)
    hmma_gemm_kernel<<<dim3(QKVN / 128, MTOT / 128), 256, GEMM_SMEM>>>(
        xh, xl, wqh, wql, nullptr, nullptr, 0);

    // 3. HMMA flash attention -> g_ah/g_al
    attn_hmma_kernel<<<dim3(BATCH * NHEADS, SEQ / 128), 256, AT_SMEM>>>();

    // 4. output projection -> out
    hmma_gemm_kernel<<<dim3(DIM / 128, MTOT / 128), 256, GEMM_SMEM>>>(
        ah, al, wph, wpl, b_proj, out, 1);
}

// round 5
// speedup vs baseline: 3.2490x; 1.0149x over previous
#include <cuda_runtime.h>
#include <cuda_fp16.h>
#include <cstdint>

#define DIM     768
#define NHEADS  12
#define HDIM    64
#define BATCH   8
#define SEQ     1024
#define MTOT    (BATCH * SEQ)      // 8192
#define QKVN    (3 * DIM)          // 2304
#define ATT_SCALE 0.125f

// ---------------------------------------------------------------------------
// Scratch (__device__ globals; no allocations allowed)
// ---------------------------------------------------------------------------
__device__ __half g_qh[BATCH * NHEADS * SEQ * HDIM], g_ql[BATCH * NHEADS * SEQ * HDIM];
__device__ __half g_kh[BATCH * NHEADS * SEQ * HDIM], g_kl[BATCH * NHEADS * SEQ * HDIM];
__device__ __half g_vh[BATCH * NHEADS * HDIM * SEQ], g_vl[BATCH * NHEADS * HDIM * SEQ]; // [B,H,D,N]
__device__ __half g_xh[MTOT * DIM], g_xl[MTOT * DIM];
__device__ __half g_wqh[QKVN * DIM], g_wql[QKVN * DIM];
__device__ __half g_wph[DIM * DIM],  g_wpl[DIM * DIM];
__device__ __half g_ah[MTOT * DIM],  g_al[MTOT * DIM];

__device__ __forceinline__ uint32_t smem_u32(const void* p) {
    uint32_t a;
    asm("{ .reg .u64 t; cvta.to.shared.u64 t, %1; cvt.u32.u64 %0, t; }"
        : "=r"(a) : "l"(p));
    return a;
}

#define SWZ(off) ((off) ^ (((off) >> 3) & 0x70))

#define LDSM_X4(r0, r1, r2, r3, addr) \
    asm volatile("ldmatrix.sync.aligned.m8n8.x4.shared.b16 {%0,%1,%2,%3}, [%4];" \
        : "=r"(r0), "=r"(r1), "=r"(r2), "=r"(r3) : "r"(addr))

__device__ __forceinline__ void mma16816(float* c, const uint32_t* a,
                                         const uint32_t* b)
{
    asm volatile("mma.sync.aligned.m16n8k16.row.col.f32.f16.f16.f32 "
        "{%0,%1,%2,%3}, {%4,%5,%6,%7}, {%8,%9}, {%0,%1,%2,%3};"
        : "+f"(c[0]), "+f"(c[1]), "+f"(c[2]), "+f"(c[3])
        : "r"(a[0]), "r"(a[1]), "r"(a[2]), "r"(a[3]), "r"(b[0]), "r"(b[1]));
}

__device__ __forceinline__ uint32_t packh2(__half x, __half y) {
    __half2 t = __half2(x, y);
    return *(uint32_t*)&t;
}
__device__ __forceinline__ void split2(float x, float y, uint32_t& hi, uint32_t& lo) {
    __half hx = __float2half(x), hy = __float2half(y);
    hi = packh2(hx, hy);
    lo = packh2(__float2half(x - __half2float(hx)),
                __float2half(y - __half2float(hy)));
}

// ---------------------------------------------------------------------------
// fp32 -> fp16 hi/lo split
// ---------------------------------------------------------------------------
__global__ __launch_bounds__(256)
void split_kernel(const float* __restrict__ src, __half* __restrict__ hi,
                  __half* __restrict__ lo, int n4)
{
    int i = blockIdx.x * blockDim.x + threadIdx.x;
    if (i >= n4) return;
    float4 v = ((const float4*)src)[i];
    float vs[4] = {v.x, v.y, v.z, v.w};
    __half h[4], l[4];
#pragma unroll
    for (int j = 0; j < 4; j++) {
        h[j] = __float2half(vs[j]);
        l[j] = __float2half(vs[j] - __half2float(h[j]));
    }
    __half2* hp = (__half2*)(hi + i * 4);
    __half2* lp = (__half2*)(lo + i * 4);
    hp[0] = __half2(h[0], h[1]); hp[1] = __half2(h[2], h[3]);
    lp[0] = __half2(l[0], l[1]); lp[1] = __half2(l[2], l[3]);
}

// ---------------------------------------------------------------------------
// HMMA fp16x3 GEMM v2: D[M,N] = A[M,K] @ B[N,K]^T
// CTA tile 128x64, 8 warps (4m x 2n), warp tile 32x32, KC=64, 2-stage,
// 96KB smem + <=128 regs -> 2 CTAs/SM.
// mode 0: split-scatter q/k/v as fp16 hi/lo (Q scaled, V transposed)
// mode 1: OUT = D + bias (fp32)
// ---------------------------------------------------------------------------
#define KC        64
#define NKC       (DIM / KC)                 // 12
#define G_AH      0                          // 128 x 64h = 16KB
#define G_AL      16384
#define G_BH      32768                      // 64 x 64h = 8KB
#define G_BL      40960
#define G_STAGE   49152
#define GEMM_SMEM (2 * G_STAGE)              // 98304

// copy `rows` x 64-half tile (row stride DIM) into swizzled smem
__device__ __forceinline__ void cp_tile128(uint32_t dst, const __half* g, int tid)
{
#pragma unroll
    for (int i = 0; i < 4; i++) {
        const int p = tid + i * 256;
        const int r = p >> 3;
        const int c = p & 7;
        const uint32_t off = (uint32_t)(r * 128 + c * 16);
        const void* src = (const char*)(g + (size_t)r * DIM) + c * 16;
        asm volatile("cp.async.cg.shared.global [%0], [%1], 16;"
                     :: "r"(dst + SWZ(off)), "l"(src) : "memory");
    }
}
__device__ __forceinline__ void cp_tile64(uint32_t dst, const __half* g, int tid)
{
#pragma unroll
    for (int i = 0; i < 2; i++) {
        const int p = tid + i * 256;
        const int r = p >> 3;
        const int c = p & 7;
        const uint32_t off = (uint32_t)(r * 128 + c * 16);
        const void* src = (const char*)(g + (size_t)r * DIM) + c * 16;
        asm volatile("cp.async.cg.shared.global [%0], [%1], 16;"
                     :: "r"(dst + SWZ(off)), "l"(src) : "memory");
    }
}

__global__ __launch_bounds__(256, 2)
void hmma_gemm_kernel(const __half* __restrict__ Ah, const __half* __restrict__ Al,
                      const __half* __restrict__ Bh, const __half* __restrict__ Bl,
                      const float* __restrict__ bias, float* __restrict__ OUT,
                      int mode)
{
    extern __shared__ char smem[];
    const uint32_t sbase = smem_u32(smem);
    const int tid  = threadIdx.x;
    const int wid  = tid >> 5;
    const int lane = tid & 31;
    const int wm   = wid >> 1;          // 0..3
    const int wn   = wid & 1;           // 0..1
    const int n0   = blockIdx.x * 64;
    const int m0   = blockIdx.y * 128;

    const __half* Ah0 = Ah + (size_t)m0 * DIM;
    const __half* Al0 = Al + (size_t)m0 * DIM;
    const __half* Bh0 = Bh + (size_t)n0 * DIM;
    const __half* Bl0 = Bl + (size_t)n0 * DIM;

    float acc[2][4][4];
#pragma unroll
    for (int i = 0; i < 2; i++)
#pragma unroll
        for (int j = 0; j < 4; j++)
#pragma unroll
            for (int k = 0; k < 4; k++) acc[i][j][k] = 0.f;

    {
        cp_tile128(sbase + G_AH, Ah0, tid);
        cp_tile128(sbase + G_AL, Al0, tid);
        cp_tile64 (sbase + G_BH, Bh0, tid);
        cp_tile64 (sbase + G_BL, Bl0, tid);
        asm volatile("cp.async.commit_group;" ::: "memory");
    }

    const int a_row = wm * 32 + (lane & 15);
    const int a_kh  = (lane >> 4) * 16;
    const int b_row = wn * 32 + (lane & 7) + ((lane >> 4) << 3);
    const int b_kh  = ((lane >> 3) & 1) * 16;

    for (int kc = 0; kc < NKC; kc++) {
        if (kc + 1 < NKC) {
            const uint32_t st = sbase + ((kc + 1) & 1) * G_STAGE;
            const int koff = (kc + 1) * KC;
            cp_tile128(st + G_AH, Ah0 + koff, tid);
            cp_tile128(st + G_AL, Al0 + koff, tid);
            cp_tile64 (st + G_BH, Bh0 + koff, tid);
            cp_tile64 (st + G_BL, Bl0 + koff, tid);
            asm volatile("cp.async.commit_group;" ::: "memory");
            asm volatile("cp.async.wait_group 1;" ::: "memory");
        } else {
            asm volatile("cp.async.wait_group 0;" ::: "memory");
        }
        __syncthreads();

        const uint32_t st = sbase + (kc & 1) * G_STAGE;
        const uint32_t sAh = st + G_AH, sAl = st + G_AL;
        const uint32_t sBh = st + G_BH, sBl = st + G_BL;

#pragma unroll
        for (int ks = 0; ks < KC / 16; ks++) {
            uint32_t ah[2][4], al[2][4], bh[2][4], bl[2][4];
#pragma unroll
            for (int mf = 0; mf < 2; mf++) {
                uint32_t off = (uint32_t)((a_row + mf * 16) * 128 + ks * 32 + a_kh);
                LDSM_X4(ah[mf][0], ah[mf][1], ah[mf][2], ah[mf][3], sAh + SWZ(off));
                LDSM_X4(al[mf][0], al[mf][1], al[mf][2], al[mf][3], sAl + SWZ(off));
            }
#pragma unroll
            for (int nfp = 0; nfp < 2; nfp++) {
                uint32_t off = (uint32_t)((b_row + nfp * 16 - wn * 32 + wn * 32) * 128
                                          + ks * 32 + b_kh);
                (void)off;
                uint32_t o2 = (uint32_t)((b_row + nfp * 16) * 128 + ks * 32 + b_kh);
                LDSM_X4(bh[nfp][0], bh[nfp][1], bh[nfp][2], bh[nfp][3], sBh + SWZ(o2));
                LDSM_X4(bl[nfp][0], bl[nfp][1], bl[nfp][2], bl[nfp][3], sBl + SWZ(o2));
            }
#pragma unroll
            for (int mf = 0; mf < 2; mf++)
#pragma unroll
                for (int nf = 0; nf < 4; nf++) {
                    const uint32_t* Bhf = &bh[nf >> 1][(nf & 1) * 2];
                    const uint32_t* Blf = &bl[nf >> 1][(nf & 1) * 2];
                    mma16816(acc[mf][nf], ah[mf], Bhf);
                    mma16816(acc[mf][nf], al[mf], Bhf);
                    mma16816(acc[mf][nf], ah[mf], Blf);
                }
        }
        __syncthreads();
    }

    const int rbase = m0 + wm * 32 + (lane >> 2);
    const int cbase = n0 + wn * 32 + (lane & 3) * 2;

    if (mode == 0) {
        const int sel = n0 / DIM;
        const int h   = (n0 % DIM) >> 6;
#pragma unroll
        for (int nf = 0; nf < 4; nf++) {
            const int gc = cbase + nf * 8;
            const int d  = gc & 63;
#pragma unroll
            for (int mf = 0; mf < 2; mf++) {
#pragma unroll
                for (int rr = 0; rr < 2; rr++) {
                    const int m = rbase + mf * 16 + rr * 8;
                    const int b = m >> 10;
                    const int n = m & 1023;
                    float v0 = acc[mf][nf][rr * 2];
                    float v1 = acc[mf][nf][rr * 2 + 1];
                    if (sel == 0) { v0 *= ATT_SCALE; v1 *= ATT_SCALE; }
                    __half h0 = __float2half(v0), h1 = __float2half(v1);
                    __half l0 = __float2half(v0 - __half2float(h0));
                    __half l1 = __float2half(v1 - __half2float(h1));
                    if (sel < 2) {
                        const size_t a = ((size_t)((b * NHEADS + h) * SEQ + n)) * HDIM + d;
                        __half* Hp = sel ? g_kh : g_qh;
                        __half* Lp = sel ? g_kl : g_ql;
                        *(__half2*)(Hp + a) = __half2(h0, h1);
                        *(__half2*)(Lp + a) = __half2(l0, l1);
                    } else {
                        const size_t a = ((size_t)((b * NHEADS + h) * HDIM + d)) * SEQ + n;
                        g_vh[a] = h0; g_vh[a + SEQ] = h1;
                        g_vl[a] = l0; g_vl[a + SEQ] = l1;
                    }
                }
            }
        }
    } else {
#pragma unroll
        for (int nf = 0; nf < 4; nf++) {
            const int gc = cbase + nf * 8;
            const float2 bv = *(const float2*)(bias + gc);
#pragma unroll
            for (int mf = 0; mf < 2; mf++) {
#pragma unroll
                for (int rr = 0; rr < 2; rr++) {
                    const int m = rbase + mf * 16 + rr * 8;
                    float* p = OUT + (size_t)m * DIM + gc;
                    *(float2*)p = make_float2(acc[mf][nf][rr * 2] + bv.x,
                                              acc[mf][nf][rr * 2 + 1] + bv.y);
                }
            }
        }
    }
}

// ---------------------------------------------------------------------------
// HMMA fp16x3 flash attention v2. CTA = (bh, 128-q tile), 8 warps,
// warp = 16 rows x 64 cols; KV j-tile 64, 2-stage; 96KB smem -> 2 CTAs/SM.
// ---------------------------------------------------------------------------
#define A_QH     0                 // 128 x 64h = 16KB
#define A_QL     16384
#define A_ST     32768             // stage: KH 0, KL 8192, VH 16384, VL 24576
#define A_STAGEB 32768
#define A_SMEM   (A_ST + 2 * A_STAGEB)   // 98304

// 64x64-half tile, row stride 64 (q/k hi/lo layout)
__device__ __forceinline__ void cp_kv64(uint32_t dst, const __half* g, int tid)
{
#pragma unroll
    for (int i = 0; i < 2; i++) {
        const int p = tid + i * 256;
        const int r = p >> 3;
        const int c = p & 7;
        const uint32_t off = (uint32_t)(r * 128 + c * 16);
        const void* src = (const char*)(g + (size_t)r * 64) + c * 16;
        asm volatile("cp.async.cg.shared.global [%0], [%1], 16;"
                     :: "r"(dst + SWZ(off)), "l"(src) : "memory");
    }
}
// 128x64-half Q tile
__device__ __forceinline__ void cp_q128(uint32_t dst, const __half* g, int tid)
{
#pragma unroll
    for (int i = 0; i < 4; i++) {
        const int p = tid + i * 256;
        const int r = p >> 3;
        const int c = p & 7;
        const uint32_t off = (uint32_t)(r * 128 + c * 16);
        const void* src = (const char*)(g + (size_t)r * 64) + c * 16;
        asm volatile("cp.async.cg.shared.global [%0], [%1], 16;"
                     :: "r"(dst + SWZ(off)), "l"(src) : "memory");
    }
}
// V^T slab: 64 d-rows x 64 seq cols from [D][SEQ] layout
__device__ __forceinline__ void cp_v64(uint32_t dst, const __half* g, int j0, int tid)
{
#pragma unroll
    for (int i = 0; i < 2; i++) {
        const int p = tid + i * 256;
        const int d = p >> 3;
        const int c = p & 7;
        const void* src = g + (size_t)d * SEQ + j0 + c * 8;
        const uint32_t off = (uint32_t)(d * 128 + c * 16);
        asm volatile("cp.async.cg.shared.global [%0], [%1], 16;"
                     :: "r"(dst + SWZ(off)), "l"(src) : "memory");
    }
}

__global__ __launch_bounds__(256, 2)
void attn_hmma_kernel()
{
    extern __shared__ char smem[];
    const uint32_t sb = smem_u32(smem);
    const int tid = threadIdx.x, wid = tid >> 5, lane = tid & 31;
    const int bh = blockIdx.x, qt = blockIdx.y;

    const __half* qhg = g_qh + ((size_t)bh * SEQ + qt * 128) * HDIM;
    const __half* qlg = g_ql + ((size_t)bh * SEQ + qt * 128) * HDIM;
    const __half* khg = g_kh + (size_t)bh * SEQ * HDIM;
    const __half* klg = g_kl + (size_t)bh * SEQ * HDIM;
    const __half* vhg = g_vh + (size_t)bh * HDIM * SEQ;
    const __half* vlg = g_vl + (size_t)bh * HDIM * SEQ;

    cp_q128(sb + A_QH, qhg, tid);
    cp_q128(sb + A_QL, qlg, tid);
    {
        const uint32_t st = sb + A_ST;
        cp_kv64(st,         khg, tid);
        cp_kv64(st + 8192,  klg, tid);
        cp_v64 (st + 16384, vhg, 0, tid);
        cp_v64 (st + 24576, vlg, 0, tid);
        asm volatile("cp.async.commit_group;" ::: "memory");
    }
    {
        const uint32_t st = sb + A_ST + A_STAGEB;
        cp_kv64(st,         khg + 64 * HDIM, tid);
        cp_kv64(st + 8192,  klg + 64 * HDIM, tid);
        cp_v64 (st + 16384, vhg, 64, tid);
        cp_v64 (st + 24576, vlg, 64, tid);
        asm volatile("cp.async.commit_group;" ::: "memory");
    }

    float m0 = -1e30f, m1 = -1e30f, l0 = 0.f, l1 = 0.f;
    float oacc[8][4];
#pragma unroll
    for (int i = 0; i < 8; i++)
#pragma unroll
        for (int j = 0; j < 4; j++) oacc[i][j] = 0.f;

    uint32_t qfh[4][4], qfl[4][4];
    const int brow = (lane & 7) + ((lane >> 4) << 3);
    const int bkh  = ((lane >> 3) & 1) * 16;
    const int NJ = SEQ / 64;   // 16

    for (int j = 0; j < NJ; j++) {
        if (j < NJ - 1) asm volatile("cp.async.wait_group 1;" ::: "memory");
        else            asm volatile("cp.async.wait_group 0;" ::: "memory");
        __syncthreads();

        if (j == 0) {
            const int a_row = wid * 16 + (lane & 15);
            const int a_kh  = (lane >> 4) * 16;
#pragma unroll
            for (int ks = 0; ks < 4; ks++) {
                uint32_t off = (uint32_t)(a_row * 128 + ks * 32 + a_kh);
                LDSM_X4(qfh[ks][0], qfh[ks][1], qfh[ks][2], qfh[ks][3],
                        sb + A_QH + SWZ(off));
                LDSM_X4(qfl[ks][0], qfl[ks][1], qfl[ks][2], qfl[ks][3],
                        sb + A_QL + SWZ(off));
            }
        }

        const uint32_t st  = sb + A_ST + (j & 1) * A_STAGEB;
        const uint32_t sKH = st, sKL = st + 8192;
        const uint32_t sVH = st + 16384, sVL = st + 24576;

        // ---- S = Qs @ K^T ----
        float sacc[8][4];
#pragma unroll
        for (int i = 0; i < 8; i++)
#pragma unroll
            for (int k = 0; k < 4; k++) sacc[i][k] = 0.f;

#pragma unroll
        for (int ks = 0; ks < 4; ks++) {
#pragma unroll
            for (int nfp = 0; nfp < 4; nfp++) {
                uint32_t kh[4], kl[4];
                uint32_t off = (uint32_t)((nfp * 16 + brow) * 128 + ks * 32 + bkh);
                LDSM_X4(kh[0], kh[1], kh[2], kh[3], sKH + SWZ(off));
                LDSM_X4(kl[0], kl[1], kl[2], kl[3], sKL + SWZ(off));
                mma16816(sacc[2 * nfp],     qfh[ks], kh);
                mma16816(sacc[2 * nfp + 1], qfh[ks], kh + 2);
                mma16816(sacc[2 * nfp],     qfl[ks], kh);
                mma16816(sacc[2 * nfp + 1], qfl[ks], kh + 2);
                mma16816(sacc[2 * nfp],     qfh[ks], kl);
                mma16816(sacc[2 * nfp + 1], qfh[ks], kl + 2);
            }
        }

        // ---- online softmax (rows lane/4 and lane/4+8) ----
        float mx0 = m0, mx1 = m1;
#pragma unroll
        for (int nf = 0; nf < 8; nf++) {
            mx0 = fmaxf(mx0, fmaxf(sacc[nf][0], sacc[nf][1]));
            mx1 = fmaxf(mx1, fmaxf(sacc[nf][2], sacc[nf][3]));
        }
        mx0 = fmaxf(mx0, __shfl_xor_sync(0xffffffff, mx0, 1));
        mx0 = fmaxf(mx0, __shfl_xor_sync(0xffffffff, mx0, 2));
        mx1 = fmaxf(mx1, __shfl_xor_sync(0xffffffff, mx1, 1));
        mx1 = fmaxf(mx1, __shfl_xor_sync(0xffffffff, mx1, 2));

        const float fac0 = __expf(m0 - mx0);
        const float fac1 = __expf(m1 - mx1);
        float sum0 = 0.f, sum1 = 0.f;
#pragma unroll
        for (int nf = 0; nf < 8; nf++) {
            float e0 = __expf(sacc[nf][0] - mx0); sacc[nf][0] = e0; sum0 += e0;
            float e1 = __expf(sacc[nf][1] - mx0); sacc[nf][1] = e1; sum0 += e1;
            float e2 = __expf(sacc[nf][2] - mx1); sacc[nf][2] = e2; sum1 += e2;
            float e3 = __expf(sacc[nf][3] - mx1); sacc[nf][3] = e3; sum1 += e3;
        }
        sum0 += __shfl_xor_sync(0xffffffff, sum0, 1);
        sum0 += __shfl_xor_sync(0xffffffff, sum0, 2);
        sum1 += __shfl_xor_sync(0xffffffff, sum1, 1);
        sum1 += __shfl_xor_sync(0xffffffff, sum1, 2);
        l0 = l0 * fac0 + sum0; m0 = mx0;
        l1 = l1 * fac1 + sum1; m1 = mx1;

#pragma unroll
        for (int onf = 0; onf < 8; onf++) {
            oacc[onf][0] *= fac0; oacc[onf][1] *= fac0;
            oacc[onf][2] *= fac1; oacc[onf][3] *= fac1;
        }

        // ---- O += P @ V ----
#pragma unroll
        for (int ks = 0; ks < 4; ks++) {
            uint32_t ah[4], al[4];
            split2(sacc[2 * ks][0],     sacc[2 * ks][1],     ah[0], al[0]);
            split2(sacc[2 * ks][2],     sacc[2 * ks][3],     ah[1], al[1]);
            split2(sacc[2 * ks + 1][0], sacc[2 * ks + 1][1], ah[2], al[2]);
            split2(sacc[2 * ks + 1][2], sacc[2 * ks + 1][3], ah[3], al[3]);
#pragma unroll
            for (int nfp = 0; nfp < 4; nfp++) {
                uint32_t vh[4], vl[4];
                uint32_t off = (uint32_t)((nfp * 16 + brow) * 128 + ks * 32 + bkh);
                LDSM_X4(vh[0], vh[1], vh[2], vh[3], sVH + SWZ(off));
                LDSM_X4(vl[0], vl[1], vl[2], vl[3], sVL + SWZ(off));
                mma16816(oacc[2 * nfp],     ah, vh);
                mma16816(oacc[2 * nfp + 1], ah, vh + 2);
                mma16816(oacc[2 * nfp],     al, vh);
                mma16816(oacc[2 * nfp + 1], al, vh + 2);
                mma16816(oacc[2 * nfp],     ah, vl);
                mma16816(oacc[2 * nfp + 1], ah, vl + 2);
            }
        }

        __syncthreads();
        if (j + 2 < NJ) {
            const uint32_t stn = sb + A_ST + (j & 1) * A_STAGEB;
            const int j0 = (j + 2) * 64;
            cp_kv64(stn,         khg + (size_t)j0 * HDIM, tid);
            cp_kv64(stn + 8192,  klg + (size_t)j0 * HDIM, tid);
            cp_v64 (stn + 16384, vhg, j0, tid);
            cp_v64 (stn + 24576, vlg, j0, tid);
            asm volatile("cp.async.commit_group;" ::: "memory");
        }
    }

    // ---- epilogue: normalize, fp16 hi/lo split into g_ah/g_al [B,N,C] ----
    const int h = bh % NHEADS;
    const int b = bh / NHEADS;
    const int n0 = qt * 128 + wid * 16 + (lane >> 2);
    const float li0 = 1.f / l0, li1 = 1.f / l1;
#pragma unroll
    for (int onf = 0; onf < 8; onf++) {
        const int d = onf * 8 + (lane & 3) * 2;
        const size_t base0 = ((size_t)(b * SEQ + n0)) * DIM + h * HDIM + d;
        const size_t base1 = base0 + (size_t)8 * DIM;
        uint32_t hi, lo;
        split2(oacc[onf][0] * li0, oacc[onf][1] * li0, hi, lo);
        *(uint32_t*)(g_ah + base0) = hi;
        *(uint32_t*)(g_al + base0) = lo;
        split2(oacc[onf][2] * li1, oacc[onf][3] * li1, hi, lo);
        *(uint32_t*)(g_ah + base1) = hi;
        *(uint32_t*)(g_al + base1) = lo;
    }
}

// ---------------------------------------------------------------------------
extern "C" void kernel_launch(void* const* d_in, const int* in_sizes, int n_in,
                              void* d_out, int out_size)
{
    (void)in_sizes; (void)n_in; (void)out_size;
    const float* x      = (const float*)d_in[0];
    const float* w_qkv  = (const float*)d_in[1];
    const float* w_proj = (const float*)d_in[2];
    const float* b_proj = (const float*)d_in[3];
    float* out = (float*)d_out;

    cudaFuncSetAttribute(hmma_gemm_kernel, cudaFuncAttributeMaxDynamicSharedMemorySize,
                         GEMM_SMEM);
    cudaFuncSetAttribute(attn_hmma_kernel, cudaFuncAttributeMaxDynamicSharedMemorySize,
                         A_SMEM);

    __half *xh, *xl, *wqh, *wql, *wph, *wpl, *ah, *al;
    cudaGetSymbolAddress((void**)&xh,  g_xh);  cudaGetSymbolAddress((void**)&xl,  g_xl);
    cudaGetSymbolAddress((void**)&wqh, g_wqh); cudaGetSymbolAddress((void**)&wql, g_wql);
    cudaGetSymbolAddress((void**)&wph, g_wph); cudaGetSymbolAddress((void**)&wpl, g_wpl);
    cudaGetSymbolAddress((void**)&ah,  g_ah);  cudaGetSymbolAddress((void**)&al,  g_al);

    // 1. hi/lo splits
    split_kernel<<<(MTOT * DIM / 4 + 255) / 256, 256>>>(x, xh, xl, MTOT * DIM / 4);
    split_kernel<<<(QKVN * DIM / 4 + 255) / 256, 256>>>(w_qkv, wqh, wql, QKVN * DIM / 4);
    split_kernel<<<(DIM * DIM / 4 + 255) / 256, 256>>>(w_proj, wph, wpl, DIM * DIM / 4);

    // 2. QKV GEMM -> fp16 hi/lo q/k/v (Q scaled, V transposed)
    hmma_gemm_kernel<<<dim3(QKVN / 64, MTOT / 128), 256, GEMM_SMEM>>>(
        xh, xl, wqh, wql, nullptr, nullptr, 0);

    // 3. HMMA flash attention -> g_ah/g_al
    attn_hmma_kernel<<<dim3(BATCH * NHEADS, SEQ / 128), 256, A_SMEM>>>();

    // 4. output projection -> out
    hmma_gemm_kernel<<<dim3(DIM / 64, MTOT / 128), 256, GEMM_SMEM>>>(
        ah, al, wph, wpl, b_proj, out, 1);
}